// round 6
// baseline (speedup 1.0000x reference)
#include <cuda_runtime.h>

// OrbitalSpectralConv: B=8, C=128, H=W=128; kept modes: 32 kx rows x 17 ky cols.
// kx rows: mk 0..16 -> kx = mk; mk 17..31 -> kx = mk+96 == -(32-mk) mod 128.
#define NKY   17
#define NMK   32
#define NMODE 544           // 32*17
#define NSLICE 1024         // B*C

// Scratch (allocation banned -> device globals).
__device__ float2 g_G [NSLICE * NKY * 128];      // 17.8 MB  w-DFT intermediate
__device__ float2 g_Xf[128 * NMODE * 8];         // 4.45 MB  layout [c][m][b]
__device__ float2 g_Y [NSLICE * NMODE];          // 4.45 MB  layout [b][c][m]

// ===========================================================================
// Kernel 1a: w-DFT per (b,c) slice, even/odd folded, half-slice staging.
//   G[ky][h] = Sp[h][0] + (-1)^ky Sp[h][64]
//            + sum_{w=1..63} Sp[h][w] cos(t ky w) - i Sm[h][w] sin(t ky w)
//   Sp[w]=x[w]+x[128-w], Sm[w]=x[w]-x[128-w], t=2pi/128.
// Block 256 = 64 h x 4 ky-groups of 5 (dups at ky=4,8,12 write identical data).
// ===========================================================================
__global__ __launch_bounds__(256) void k_fwd1(const float* __restrict__ X) {
    __shared__ float2 T1[64 * 18];   // T1[w][ky] = (cos,sin)(2pi w ky/128)
    __shared__ float  Sp[64 * 65];
    __shared__ float  Sm[64 * 65];

    const int tid = threadIdx.x;
    for (int i = tid; i < 64 * NKY; i += 256) {
        int w = i / NKY, ky = i - w * NKY;
        float s, c;
        sincospif((float)((w * ky) & 127) * (2.0f / 128.0f), &s, &c);
        T1[w * 18 + ky] = make_float2(c, s);
    }

    const float* Xp = X + (size_t)blockIdx.x * 16384;
    float2* Gp = g_G + (size_t)blockIdx.x * (NKY * 128);

    const int hl = tid & 63;
    const int kb = (tid >> 6) * 4;   // ky groups: 0-4, 4-8, 8-12, 12-16

    for (int half = 0; half < 2; half++) {
        for (int i = tid; i < 64 * 64; i += 256) {
            int hr = i >> 6, w = i & 63;
            const float* row = Xp + (half * 64 + hr) * 128;
            float xa = row[w];
            if (w == 0) {
                Sp[hr * 65 + 0]  = xa;
                Sp[hr * 65 + 64] = row[64];
            } else {
                float xb = row[128 - w];
                Sp[hr * 65 + w] = xa + xb;
                Sm[hr * 65 + w] = xa - xb;
            }
        }
        __syncthreads();

        float gre[5], gim[5];
        float s0 = Sp[hl * 65 + 0], s64 = Sp[hl * 65 + 64];
        #pragma unroll
        for (int j = 0; j < 5; j++) {
            gre[j] = s0 + (((kb + j) & 1) ? -s64 : s64);
            gim[j] = 0.f;
        }
        #pragma unroll 7
        for (int w = 1; w < 64; w++) {
            float sp  = Sp[hl * 65 + w];
            float nsm = -Sm[hl * 65 + w];
            const float4* tp = (const float4*)(T1 + w * 18 + kb);
            float4 tA = tp[0];                                  // ky kb, kb+1
            float4 tB = tp[1];                                  // ky kb+2, kb+3
            float2 tE = *(const float2*)(T1 + w * 18 + kb + 4); // ky kb+4
            gre[0] = fmaf(tA.x, sp, gre[0]);  gim[0] = fmaf(tA.y, nsm, gim[0]);
            gre[1] = fmaf(tA.z, sp, gre[1]);  gim[1] = fmaf(tA.w, nsm, gim[1]);
            gre[2] = fmaf(tB.x, sp, gre[2]);  gim[2] = fmaf(tB.y, nsm, gim[2]);
            gre[3] = fmaf(tB.z, sp, gre[3]);  gim[3] = fmaf(tB.w, nsm, gim[3]);
            gre[4] = fmaf(tE.x, sp, gre[4]);  gim[4] = fmaf(tE.y, nsm, gim[4]);
        }
        const int h = half * 64 + hl;
        #pragma unroll
        for (int j = 0; j < 5; j++)
            Gp[(kb + j) * 128 + h] = make_float2(gre[j], gim[j]);
        __syncthreads();
    }
}

// ===========================================================================
// Kernel 1b: h-DFT, folded; emits +a and -a modes from shared trig.
//   C1=sum cos(ah) Gp_re, C2=sum cos(ah) Gp_im, S1=sum sin(ah) Gm_re, S2=...im
//   Xf[+a]=(C1+S2, C2-S1), Xf[-a]=(C1-S2, C2+S1), scaled by 1/16384.
// Writes g_Xf in [c][m][b] layout for k_mix vector loads.
// ===========================================================================
__global__ __launch_bounds__(320) void k_fwd2() {
    __shared__ float2 Gs[NKY * 128];
    __shared__ float2 tb[128];

    const int tid = threadIdx.x;
    if (tid < 128) {
        float s, c;
        sincospif((float)tid * (2.0f / 128.0f), &s, &c);
        tb[tid] = make_float2(c, s);
    }
    const float2* Gp = g_G + (size_t)blockIdx.x * (NKY * 128);
    for (int i = tid; i < NKY * 128; i += 320) Gs[i] = Gp[i];
    __syncthreads();

    const int b = blockIdx.x >> 7, c = blockIdx.x & 127;
    float2* Xfb = g_Xf + (size_t)c * (NMODE * 8) + b;
    const float inv = 1.0f / 16384.0f;

    for (int i = tid; i < 17 * NKY; i += 320) {
        int a = i / NKY, ky = i - a * NKY;
        float2 g0  = Gs[ky * 128 + 0];
        float2 g64 = Gs[ky * 128 + 64];
        float sgn = (a & 1) ? -1.f : 1.f;
        float C1 = g0.x + sgn * g64.x;
        float C2 = g0.y + sgn * g64.y;
        float S1 = 0.f, S2 = 0.f;
        int p = a;
        for (int h = 1; h < 64; h++) {
            float2 t  = tb[p & 127];
            float2 ga = Gs[ky * 128 + h];
            float2 gb = Gs[ky * 128 + 128 - h];
            float pr = ga.x + gb.x, pi = ga.y + gb.y;
            float mr = ga.x - gb.x, mi = ga.y - gb.y;
            C1 = fmaf(t.x, pr, C1);
            C2 = fmaf(t.x, pi, C2);
            S1 = fmaf(t.y, mr, S1);
            S2 = fmaf(t.y, mi, S2);
            p += a;
        }
        Xfb[(a * NKY + ky) * 8] = make_float2((C1 + S2) * inv, (C2 - S1) * inv);
        if (a >= 1 && a <= 15)
            Xfb[((32 - a) * NKY + ky) * 8] = make_float2((C1 - S2) * inv, (C2 + S1) * inv);
    }
}

// ===========================================================================
// Kernel 2: spectral channel mix, skew-Hermitian weight built on the fly.
//   Y[b,c,m] = sum_ct [(re[c,ct,m]-re[ct,c,m]) + i(im[c,ct,m]+im[ct,c,m])] Xf[b,ct,m]
// grid (17 m-tiles x 16 c-tiles), block 256 = 32 m x 8 c. Thread = (c, m),
// 8 batch complex accumulators; Xf loads are 4x LDG.128 (batches contiguous).
// ===========================================================================
__global__ __launch_bounds__(256) void k_mix(const float* __restrict__ re,
                                             const float* __restrict__ im) {
    const int mi = threadIdx.x & 31;
    const int ci = threadIdx.x >> 5;
    const int m  = blockIdx.x * 32 + mi;
    const int c  = blockIdx.y * 8 + ci;

    float yr[8], yi[8];
    #pragma unroll
    for (int b = 0; b < 8; b++) { yr[b] = 0.f; yi[b] = 0.f; }

    const float* reA = re + (size_t)c * (128 * NMODE) + m;   // [c][ct][m]
    const float* reB = re + (size_t)c * NMODE + m;           // [ct][c][m]
    const float* imA = im + (size_t)c * (128 * NMODE) + m;
    const float* imB = im + (size_t)c * NMODE + m;
    const float4* xb = (const float4*)g_Xf + (size_t)m * 4;  // [ct][m][b0..7]

    #pragma unroll 2
    for (int ct = 0; ct < 128; ct++) {
        float wre = reA[ct * NMODE] - reB[ct * (128 * NMODE)];
        float wim = imA[ct * NMODE] + imB[ct * (128 * NMODE)];
        const float4* x4 = xb + (size_t)ct * (NMODE * 4);
        float4 x0 = x4[0], x1 = x4[1], x2 = x4[2], x3 = x4[3];
        yr[0]=fmaf(wre,x0.x,fmaf(-wim,x0.y,yr[0])); yi[0]=fmaf(wre,x0.y,fmaf(wim,x0.x,yi[0]));
        yr[1]=fmaf(wre,x0.z,fmaf(-wim,x0.w,yr[1])); yi[1]=fmaf(wre,x0.w,fmaf(wim,x0.z,yi[1]));
        yr[2]=fmaf(wre,x1.x,fmaf(-wim,x1.y,yr[2])); yi[2]=fmaf(wre,x1.y,fmaf(wim,x1.x,yi[2]));
        yr[3]=fmaf(wre,x1.z,fmaf(-wim,x1.w,yr[3])); yi[3]=fmaf(wre,x1.w,fmaf(wim,x1.z,yi[3]));
        yr[4]=fmaf(wre,x2.x,fmaf(-wim,x2.y,yr[4])); yi[4]=fmaf(wre,x2.y,fmaf(wim,x2.x,yi[4]));
        yr[5]=fmaf(wre,x2.z,fmaf(-wim,x2.w,yr[5])); yi[5]=fmaf(wre,x2.w,fmaf(wim,x2.z,yi[5]));
        yr[6]=fmaf(wre,x3.x,fmaf(-wim,x3.y,yr[6])); yi[6]=fmaf(wre,x3.y,fmaf(wim,x3.x,yi[6]));
        yr[7]=fmaf(wre,x3.z,fmaf(-wim,x3.w,yr[7])); yi[7]=fmaf(wre,x3.w,fmaf(wim,x3.z,yi[7]));
    }
    #pragma unroll
    for (int b = 0; b < 8; b++)
        g_Y[(size_t)(b * 128 + c) * NMODE + m] = make_float2(yr[b], yi[b]);
}

// ===========================================================================
// Kernel 3: inverse per (b,c) slice, folded (same as R5 — correct & compact).
// ===========================================================================
__global__ __launch_bounds__(320) void k_inv(float* __restrict__ out) {
    __shared__ float2 tb[128];
    __shared__ float2 Pa[NKY][NKY];     // [a][ky]
    __shared__ float2 Ma[NKY][NKY];
    __shared__ float2 Zs[128][18];      // padded for float4 row loads

    const int tid = threadIdx.x;
    if (tid < 128) {
        float s, c;
        sincospif((float)tid * (2.0f / 128.0f), &s, &c);
        tb[tid] = make_float2(c, s);
    }

    const float2* Yp = g_Y + (size_t)blockIdx.x * NMODE;
    for (int i = tid; i < 17 * NKY; i += 320) {
        int a = i / NKY, ky = i - a * NKY;
        float2 yp = Yp[a * NKY + ky];
        float2 P, M;
        if (a == 0)       { P = yp; M = make_float2(0.f, 0.f); }
        else if (a == 16) { P = yp; M = yp; }
        else {
            float2 yn = Yp[(32 - a) * NKY + ky];
            P = make_float2(yp.x + yn.x, yp.y + yn.y);
            M = make_float2(yp.x - yn.x, yp.y - yn.y);
        }
        Pa[a][ky] = P;
        Ma[a][ky] = M;
    }
    __syncthreads();

    // Phase A: kx -> h synthesis (emit h and 128-h)
    for (int i = tid; i < 65 * NKY; i += 320) {
        int h = i / NKY, ky = i - h * NKY;
        float C1 = 0.f, C2 = 0.f, S1 = 0.f, S2 = 0.f;
        int p = 0;
        #pragma unroll
        for (int a = 0; a < NKY; a++) {
            float2 t = tb[p & 127];
            float2 P = Pa[a][ky];
            float2 M = Ma[a][ky];
            C1 = fmaf(t.x, P.x, C1);
            C2 = fmaf(t.x, P.y, C2);
            S1 = fmaf(t.y, M.x, S1);
            S2 = fmaf(t.y, M.y, S2);
            p += h;
        }
        Zs[h][ky] = make_float2(C1 - S2, C2 + S1);
        if (h >= 1 && h <= 63)
            Zs[128 - h][ky] = make_float2(C1 + S2, C2 - S1);
    }
    __syncthreads();

    float* op = out + (size_t)blockIdx.x * 16384;

    if (tid < 256) {
        // Phase B: ky -> w synthesis (c2r), emit w and 128-w
        const int w  = tid & 63;
        const int h0 = (tid >> 6) * 32;
        float ck[NKY], sk[NKY];
        #pragma unroll
        for (int ky = 0; ky < NKY; ky++) {
            float2 t = tb[(ky * w) & 127];
            float a = ky ? 2.0f : 1.0f;
            ck[ky] = a * t.x;
            sk[ky] = a * t.y;
        }
        for (int h = h0; h < h0 + 32; h++) {
            const float4* zp = (const float4*)(&Zs[h][0]);
            float C = 0.f, S = 0.f;
            #pragma unroll
            for (int j = 0; j < 8; j++) {
                float4 q = zp[j];
                C = fmaf(ck[2 * j],     q.x, C);
                S = fmaf(sk[2 * j],     q.y, S);
                C = fmaf(ck[2 * j + 1], q.z, C);
                S = fmaf(sk[2 * j + 1], q.w, S);
            }
            float2 z16 = Zs[h][16];
            C = fmaf(ck[16], z16.x, C);
            S = fmaf(sk[16], z16.y, S);
            op[h * 128 + w] = C - S;
            if (w) op[h * 128 + 128 - w] = C + S;
        }
    } else {
        // w = 64 column: cos(pi ky) = (-1)^ky, sin = 0
        int h2 = (tid - 256) * 2;
        #pragma unroll
        for (int r = 0; r < 2; r++) {
            int h = h2 + r;
            float E = 0.f;
            #pragma unroll
            for (int ky = 0; ky < NKY; ky++) {
                float a = ky ? 2.0f : 1.0f;
                float c = (ky & 1) ? -a : a;
                E = fmaf(c, Zs[h][ky].x, E);
            }
            op[h * 128 + 64] = E;
        }
    }
}

extern "C" void kernel_launch(void* const* d_in, const int* in_sizes, int n_in,
                              void* d_out, int out_size) {
    const float* X  = (const float*)d_in[0];
    const float* re = (const float*)d_in[1];
    const float* im = (const float*)d_in[2];
    float* out = (float*)d_out;

    k_fwd1<<<NSLICE, 256>>>(X);
    k_fwd2<<<NSLICE, 320>>>();
    k_mix<<<dim3(17, 16), 256>>>(re, im);
    k_inv<<<NSLICE, 320>>>(out);
}

// round 7
// speedup vs baseline: 1.5800x; 1.5800x over previous
#include <cuda_runtime.h>

// OrbitalSpectralConv: B=8, C=128, H=W=128; kept modes: 32 kx rows x 17 ky cols.
// kx rows: mk 0..16 -> kx = mk; mk 17..31 -> kx = mk+96 == -(32-mk) mod 128.
#define NKY   17
#define NMK   32
#define NMODE 544           // 32*17
#define NSLICE 1024         // B*C

// Scratch (allocation banned -> device globals).
__device__ float2 g_G [NSLICE * NKY * 128];      // 17.8 MB  [slice][ky][h]
__device__ float2 g_Xf[128 * NMODE * 8];         // 4.45 MB  [c][m][b]
__device__ float2 g_Y [NSLICE * NMODE];          // 4.45 MB  [b][c][m]
__device__ float2 g_Z [NSLICE * 128 * NKY];      // 17.8 MB  [slice][h][ky]

// ===========================================================================
// Kernel 1a: w-DFT per (b,c) slice, even/odd folded, half-slice staging.
//   G[ky][h] = Sp[h][0] + (-1)^ky Sp[h][64]
//            + sum_{w=1..63} Sp[h][w] cos(t ky w) - i Sm[h][w] sin(t ky w)
//   Sp[w]=x[w]+x[128-w], Sm[w]=x[w]-x[128-w], t=2pi/128.
// Block 256 = 64 h x 4 ky-groups of 5 (dups at ky=4,8,12 write identical data).
// ===========================================================================
__global__ __launch_bounds__(256) void k_fwd1(const float* __restrict__ X) {
    __shared__ float2 T1[64 * 18];   // T1[w][ky] = (cos,sin)(2pi w ky/128)
    __shared__ float  Sp[64 * 65];
    __shared__ float  Sm[64 * 65];

    const int tid = threadIdx.x;
    for (int i = tid; i < 64 * NKY; i += 256) {
        int w = i / NKY, ky = i - w * NKY;
        float s, c;
        sincospif((float)((w * ky) & 127) * (2.0f / 128.0f), &s, &c);
        T1[w * 18 + ky] = make_float2(c, s);
    }

    const float* Xp = X + (size_t)blockIdx.x * 16384;
    float2* Gp = g_G + (size_t)blockIdx.x * (NKY * 128);

    const int hl = tid & 63;
    const int kb = (tid >> 6) * 4;   // ky groups: 0-4, 4-8, 8-12, 12-16

    for (int half = 0; half < 2; half++) {
        for (int i = tid; i < 64 * 64; i += 256) {
            int hr = i >> 6, w = i & 63;
            const float* row = Xp + (half * 64 + hr) * 128;
            float xa = row[w];
            if (w == 0) {
                Sp[hr * 65 + 0]  = xa;
                Sp[hr * 65 + 64] = row[64];
            } else {
                float xb = row[128 - w];
                Sp[hr * 65 + w] = xa + xb;
                Sm[hr * 65 + w] = xa - xb;
            }
        }
        __syncthreads();

        float gre[5], gim[5];
        float s0 = Sp[hl * 65 + 0], s64 = Sp[hl * 65 + 64];
        #pragma unroll
        for (int j = 0; j < 5; j++) {
            gre[j] = s0 + (((kb + j) & 1) ? -s64 : s64);
            gim[j] = 0.f;
        }
        #pragma unroll 7
        for (int w = 1; w < 64; w++) {
            float sp  = Sp[hl * 65 + w];
            float nsm = -Sm[hl * 65 + w];
            const float4* tp = (const float4*)(T1 + w * 18 + kb);
            float4 tA = tp[0];
            float4 tB = tp[1];
            float2 tE = *(const float2*)(T1 + w * 18 + kb + 4);
            gre[0] = fmaf(tA.x, sp, gre[0]);  gim[0] = fmaf(tA.y, nsm, gim[0]);
            gre[1] = fmaf(tA.z, sp, gre[1]);  gim[1] = fmaf(tA.w, nsm, gim[1]);
            gre[2] = fmaf(tB.x, sp, gre[2]);  gim[2] = fmaf(tB.y, nsm, gim[2]);
            gre[3] = fmaf(tB.z, sp, gre[3]);  gim[3] = fmaf(tB.w, nsm, gim[3]);
            gre[4] = fmaf(tE.x, sp, gre[4]);  gim[4] = fmaf(tE.y, nsm, gim[4]);
        }
        const int h = half * 64 + hl;
        #pragma unroll
        for (int j = 0; j < 5; j++)
            Gp[(kb + j) * 128 + h] = make_float2(gre[j], gim[j]);
        __syncthreads();
    }
}

// ===========================================================================
// Kernel 1b: h-DFT, folded; emits +a and -a modes from shared trig.
// Smem layout transposed to Gs[h*17+ky] -> compute-loop lanes have
// consecutive ky => conflict-free; trig lookup broadcasts (h shared).
//   Xf[+a]=(C1+S2, C2-S1), Xf[-a]=(C1-S2, C2+S1), scaled by 1/16384.
// Writes g_Xf in [c][m][b] layout for k_mix vector loads.
// ===========================================================================
__global__ __launch_bounds__(320) void k_fwd2() {
    __shared__ float2 Gs[128 * NKY];    // [h][ky]
    __shared__ float2 tb[128];

    const int tid = threadIdx.x;
    if (tid < 128) {
        float s, c;
        sincospif((float)tid * (2.0f / 128.0f), &s, &c);
        tb[tid] = make_float2(c, s);
    }
    const float2* Gp = g_G + (size_t)blockIdx.x * (NKY * 128);
    for (int i = tid; i < NKY * 128; i += 320) {
        int ky = i >> 7, h = i & 127;
        Gs[h * NKY + ky] = Gp[i];       // coalesced read, conflict-free write
    }
    __syncthreads();

    const int b = blockIdx.x >> 7, c = blockIdx.x & 127;
    float2* Xfb = g_Xf + (size_t)c * (NMODE * 8) + b;
    const float inv = 1.0f / 16384.0f;

    if (tid < 17 * NKY) {
        const int a = tid / NKY, ky = tid - a * NKY;
        float2 g0  = Gs[0 * NKY + ky];
        float2 g64 = Gs[64 * NKY + ky];
        float sgn = (a & 1) ? -1.f : 1.f;
        float C1 = g0.x + sgn * g64.x;
        float C2 = g0.y + sgn * g64.y;
        float S1 = 0.f, S2 = 0.f;
        int p = a;
        for (int h = 1; h < 64; h++) {
            float2 t  = tb[p & 127];
            float2 ga = Gs[h * NKY + ky];
            float2 gb = Gs[(128 - h) * NKY + ky];
            float pr = ga.x + gb.x, pi = ga.y + gb.y;
            float mr = ga.x - gb.x, mi = ga.y - gb.y;
            C1 = fmaf(t.x, pr, C1);
            C2 = fmaf(t.x, pi, C2);
            S1 = fmaf(t.y, mr, S1);
            S2 = fmaf(t.y, mi, S2);
            p += a;
        }
        Xfb[(a * NKY + ky) * 8] = make_float2((C1 + S2) * inv, (C2 - S1) * inv);
        if (a >= 1 && a <= 15)
            Xfb[((32 - a) * NKY + ky) * 8] = make_float2((C1 - S2) * inv, (C2 + S1) * inv);
    }
}

// ===========================================================================
// Kernel 2: spectral channel mix, skew-Hermitian weight built on the fly.
//   Y[b,c,m] = sum_ct [(re[c,ct,m]-re[ct,c,m]) + i(im[c,ct,m]+im[ct,c,m])] Xf[b,ct,m]
// grid (17 m-tiles x 32 c-tiles), block 128 = 32 m x 4 c. Thread = (c, m),
// 8 batch complex accumulators; Xf loads are 4x LDG.128 (batches contiguous).
// ===========================================================================
__global__ __launch_bounds__(128) void k_mix(const float* __restrict__ re,
                                             const float* __restrict__ im) {
    const int mi = threadIdx.x & 31;
    const int ci = threadIdx.x >> 5;
    const int m  = blockIdx.x * 32 + mi;
    const int c  = blockIdx.y * 4 + ci;

    float yr[8], yi[8];
    #pragma unroll
    for (int b = 0; b < 8; b++) { yr[b] = 0.f; yi[b] = 0.f; }

    const float* reA = re + (size_t)c * (128 * NMODE) + m;   // [c][ct][m]
    const float* reB = re + (size_t)c * NMODE + m;           // [ct][c][m]
    const float* imA = im + (size_t)c * (128 * NMODE) + m;
    const float* imB = im + (size_t)c * NMODE + m;
    const float4* xb = (const float4*)g_Xf + (size_t)m * 4;  // [ct][m][b0..7]

    #pragma unroll 2
    for (int ct = 0; ct < 128; ct++) {
        float wre = reA[ct * NMODE] - reB[ct * (128 * NMODE)];
        float wim = imA[ct * NMODE] + imB[ct * (128 * NMODE)];
        const float4* x4 = xb + (size_t)ct * (NMODE * 4);
        float4 x0 = x4[0], x1 = x4[1], x2 = x4[2], x3 = x4[3];
        yr[0]=fmaf(wre,x0.x,fmaf(-wim,x0.y,yr[0])); yi[0]=fmaf(wre,x0.y,fmaf(wim,x0.x,yi[0]));
        yr[1]=fmaf(wre,x0.z,fmaf(-wim,x0.w,yr[1])); yi[1]=fmaf(wre,x0.w,fmaf(wim,x0.z,yi[1]));
        yr[2]=fmaf(wre,x1.x,fmaf(-wim,x1.y,yr[2])); yi[2]=fmaf(wre,x1.y,fmaf(wim,x1.x,yi[2]));
        yr[3]=fmaf(wre,x1.z,fmaf(-wim,x1.w,yr[3])); yi[3]=fmaf(wre,x1.w,fmaf(wim,x1.z,yi[3]));
        yr[4]=fmaf(wre,x2.x,fmaf(-wim,x2.y,yr[4])); yi[4]=fmaf(wre,x2.y,fmaf(wim,x2.x,yi[4]));
        yr[5]=fmaf(wre,x2.z,fmaf(-wim,x2.w,yr[5])); yi[5]=fmaf(wre,x2.w,fmaf(wim,x2.z,yi[5]));
        yr[6]=fmaf(wre,x3.x,fmaf(-wim,x3.y,yr[6])); yi[6]=fmaf(wre,x3.y,fmaf(wim,x3.x,yi[6]));
        yr[7]=fmaf(wre,x3.z,fmaf(-wim,x3.w,yr[7])); yi[7]=fmaf(wre,x3.w,fmaf(wim,x3.z,yi[7]));
    }
    #pragma unroll
    for (int b = 0; b < 8; b++)
        g_Y[(size_t)(b * 128 + c) * NMODE + m] = make_float2(yr[b], yi[b]);
}

// ===========================================================================
// Kernel 3a: kx -> h synthesis (folded), writes Z[h][ky] to global.
//   P[a]=Y[+a]+Y[-a], M[a]=Y[+a]-Y[-a]
//   Z[h]=(C1-S2, C2+S1), Z[128-h]=(C1+S2, C2-S1),
//   C1=sum cos(ah)P_re, C2=sum cos(ah)P_im, S1=sum sin(ah)M_re, S2=...M_im
// ===========================================================================
__global__ __launch_bounds__(320) void k_inv1() {
    __shared__ float2 tb[128];
    __shared__ float2 Pa[NKY * NKY];     // [a][ky]
    __shared__ float2 Ma[NKY * NKY];

    const int tid = threadIdx.x;
    if (tid < 128) {
        float s, c;
        sincospif((float)tid * (2.0f / 128.0f), &s, &c);
        tb[tid] = make_float2(c, s);
    }

    const float2* Yp = g_Y + (size_t)blockIdx.x * NMODE;
    if (tid < 17 * NKY) {
        int a = tid / NKY, ky = tid - a * NKY;
        float2 yp = Yp[a * NKY + ky];
        float2 P, M;
        if (a == 0)       { P = yp; M = make_float2(0.f, 0.f); }
        else if (a == 16) { P = yp; M = yp; }
        else {
            float2 yn = Yp[(32 - a) * NKY + ky];
            P = make_float2(yp.x + yn.x, yp.y + yn.y);
            M = make_float2(yp.x - yn.x, yp.y - yn.y);
        }
        Pa[a * NKY + ky] = P;
        Ma[a * NKY + ky] = M;
    }
    __syncthreads();

    float2* Zp = g_Z + (size_t)blockIdx.x * (128 * NKY);
    for (int i = tid; i < 65 * NKY; i += 320) {
        int h = i / NKY, ky = i - h * NKY;
        float C1 = 0.f, C2 = 0.f, S1 = 0.f, S2 = 0.f;
        int p = 0;
        #pragma unroll
        for (int a = 0; a < NKY; a++) {
            float2 t = tb[p & 127];
            float2 P = Pa[a * NKY + ky];
            float2 M = Ma[a * NKY + ky];
            C1 = fmaf(t.x, P.x, C1);
            C2 = fmaf(t.x, P.y, C2);
            S1 = fmaf(t.y, M.x, S1);
            S2 = fmaf(t.y, M.y, S2);
            p += h;
        }
        Zp[h * NKY + ky] = make_float2(C1 - S2, C2 + S1);
        if (h >= 1 && h <= 63)
            Zp[(128 - h) * NKY + ky] = make_float2(C1 + S2, C2 - S1);
    }
}

// ===========================================================================
// Kernel 3b: ky -> w synthesis (c2r), emit w and 128-w; then w=64 column.
//   out[h][w] = C - S, out[h][128-w] = C + S
//   C = sum a_ky Zre cos(t ky w), S = sum a_ky Zim sin(t ky w), a_0=1 else 2.
//   (c2r ignores Im(Z[.,0]) since sin(0)=0.)
// ===========================================================================
__global__ __launch_bounds__(256) void k_inv2(float* __restrict__ out) {
    __shared__ float2 tb[128];
    __shared__ float2 Zs[128][18];      // pad 18 -> 144B rows, 16B-aligned for float4

    const int tid = threadIdx.x;
    if (tid < 128) {
        float s, c;
        sincospif((float)tid * (2.0f / 128.0f), &s, &c);
        tb[tid] = make_float2(c, s);
    }
    const float2* Zp = g_Z + (size_t)blockIdx.x * (128 * NKY);
    for (int i = tid; i < 128 * NKY; i += 256) {
        int h = i / NKY, ky = i - h * NKY;
        Zs[h][ky] = Zp[i];
    }
    __syncthreads();

    float* op = out + (size_t)blockIdx.x * 16384;

    const int w  = tid & 63;
    const int h0 = (tid >> 6) * 32;
    float ck[NKY], sk[NKY];
    #pragma unroll
    for (int ky = 0; ky < NKY; ky++) {
        float2 t = tb[(ky * w) & 127];
        float a = ky ? 2.0f : 1.0f;
        ck[ky] = a * t.x;
        sk[ky] = a * t.y;
    }
    for (int h = h0; h < h0 + 32; h++) {
        const float4* zp = (const float4*)(&Zs[h][0]);
        float C = 0.f, S = 0.f;
        #pragma unroll
        for (int j = 0; j < 8; j++) {
            float4 q = zp[j];
            C = fmaf(ck[2 * j],     q.x, C);
            S = fmaf(sk[2 * j],     q.y, S);
            C = fmaf(ck[2 * j + 1], q.z, C);
            S = fmaf(sk[2 * j + 1], q.w, S);
        }
        float2 z16 = Zs[h][16];
        C = fmaf(ck[16], z16.x, C);
        S = fmaf(sk[16], z16.y, S);
        op[h * 128 + w] = C - S;
        if (w) op[h * 128 + 128 - w] = C + S;
    }

    // w = 64 column: cos(pi ky) = (-1)^ky, sin = 0
    if (tid < 128) {
        int h = tid;
        float E = 0.f;
        #pragma unroll
        for (int ky = 0; ky < NKY; ky++) {
            float a = ky ? 2.0f : 1.0f;
            float c = (ky & 1) ? -a : a;
            E = fmaf(c, Zs[h][ky].x, E);
        }
        op[h * 128 + 64] = E;
    }
}

extern "C" void kernel_launch(void* const* d_in, const int* in_sizes, int n_in,
                              void* d_out, int out_size) {
    const float* X  = (const float*)d_in[0];
    const float* re = (const float*)d_in[1];
    const float* im = (const float*)d_in[2];
    float* out = (float*)d_out;

    k_fwd1<<<NSLICE, 256>>>(X);
    k_fwd2<<<NSLICE, 320>>>();
    k_mix<<<dim3(17, 32), 128>>>(re, im);
    k_inv1<<<NSLICE, 320>>>();
    k_inv2<<<NSLICE, 256>>>(out);
}

// round 8
// speedup vs baseline: 1.6654x; 1.0541x over previous
#include <cuda_runtime.h>

// OrbitalSpectralConv: B=8, C=128, H=W=128; kept modes: 32 kx rows x 17 ky cols.
// kx rows: mk 0..16 -> kx = mk; mk 17..31 -> kx = mk+96 == -(32-mk) mod 128.
#define NKY   17
#define NMK   32
#define NMODE 544           // 32*17
#define NSLICE 1024         // B*C

// Scratch (allocation banned -> device globals).
__device__ float2 g_G [NSLICE * NKY * 128];      // 17.8 MB  [slice][ky][h]
__device__ float2 g_Xf[128 * NMODE * 8];         // 4.45 MB  [c][m][b]
__device__ float2 g_Y [NSLICE * NMODE];          // 4.45 MB  [b][c][m]
__device__ float2 g_Z [NSLICE * 128 * NKY];      // 17.8 MB  [slice][h][ky]

// ===========================================================================
// Kernel 1a: w-DFT per (b,c) slice, even/odd folded, half-slice staging.
//   G[ky][h] = Sp[h][0] + (-1)^ky Sp[h][64]
//            + sum_{w=1..63} Sp[h][w] cos(t ky w) - i Sm[h][w] sin(t ky w)
//   Sp[w]=x[w]+x[128-w], Sm[w]=x[w]-x[128-w], t=2pi/128.
// Block 256 = 64 h x 4 ky-groups of 5 (dups at ky=4,8,12 write identical data).
// T1 lookup is a warp-broadcast (kb, w uniform per warp); Sp/Sm conflict-free.
// ===========================================================================
__global__ __launch_bounds__(256) void k_fwd1(const float* __restrict__ X) {
    __shared__ float2 T1[64 * 18];   // T1[w][ky] = (cos,sin)(2pi w ky/128)
    __shared__ float  Sp[64 * 65];
    __shared__ float  Sm[64 * 65];

    const int tid = threadIdx.x;
    for (int i = tid; i < 64 * NKY; i += 256) {
        int w = i / NKY, ky = i - w * NKY;
        float s, c;
        sincospif((float)((w * ky) & 127) * (2.0f / 128.0f), &s, &c);
        T1[w * 18 + ky] = make_float2(c, s);
    }

    const float* Xp = X + (size_t)blockIdx.x * 16384;
    float2* Gp = g_G + (size_t)blockIdx.x * (NKY * 128);

    const int hl = tid & 63;
    const int kb = (tid >> 6) * 4;   // ky groups: 0-4, 4-8, 8-12, 12-16

    for (int half = 0; half < 2; half++) {
        for (int i = tid; i < 64 * 64; i += 256) {
            int hr = i >> 6, w = i & 63;
            const float* row = Xp + (half * 64 + hr) * 128;
            float xa = row[w];
            if (w == 0) {
                Sp[hr * 65 + 0]  = xa;
                Sp[hr * 65 + 64] = row[64];
            } else {
                float xb = row[128 - w];
                Sp[hr * 65 + w] = xa + xb;
                Sm[hr * 65 + w] = xa - xb;
            }
        }
        __syncthreads();

        float gre[5], gim[5];
        float s0 = Sp[hl * 65 + 0], s64 = Sp[hl * 65 + 64];
        #pragma unroll
        for (int j = 0; j < 5; j++) {
            gre[j] = s0 + (((kb + j) & 1) ? -s64 : s64);
            gim[j] = 0.f;
        }
        #pragma unroll 7
        for (int w = 1; w < 64; w++) {
            float sp  = Sp[hl * 65 + w];
            float nsm = -Sm[hl * 65 + w];
            const float4* tp = (const float4*)(T1 + w * 18 + kb);
            float4 tA = tp[0];
            float4 tB = tp[1];
            float2 tE = *(const float2*)(T1 + w * 18 + kb + 4);
            gre[0] = fmaf(tA.x, sp, gre[0]);  gim[0] = fmaf(tA.y, nsm, gim[0]);
            gre[1] = fmaf(tA.z, sp, gre[1]);  gim[1] = fmaf(tA.w, nsm, gim[1]);
            gre[2] = fmaf(tB.x, sp, gre[2]);  gim[2] = fmaf(tB.y, nsm, gim[2]);
            gre[3] = fmaf(tB.z, sp, gre[3]);  gim[3] = fmaf(tB.w, nsm, gim[3]);
            gre[4] = fmaf(tE.x, sp, gre[4]);  gim[4] = fmaf(tE.y, nsm, gim[4]);
        }
        const int h = half * 64 + hl;
        #pragma unroll
        for (int j = 0; j < 5; j++)
            Gp[(kb + j) * 128 + h] = make_float2(gre[j], gim[j]);
        __syncthreads();
    }
}

// ===========================================================================
// Kernel 1b: h-DFT, folded, 2 slices per block, rotation-generated trig.
//   C1=sum cos(ah) Gp_re, C2=sum cos(ah) Gp_im, S1=sum sin(ah) Gm_re, S2=..im
//   Xf[+a]=(C1+S2, C2-S1), Xf[-a]=(C1-S2, C2+S1), scaled by 1/16384.
// Trig (cos aht, sin aht) advances by constant step e^{i a t} per h ->
// 4-FMA rotation recurrence, no LDS, no conflicts. Writes g_Xf [c][m][b].
// ===========================================================================
__global__ __launch_bounds__(320) void k_fwd2() {
    __shared__ float2 Gs[2][128 * NKY];     // [slice][h][ky]

    const int tid = threadIdx.x;
    const int s0  = blockIdx.x * 2;

    #pragma unroll
    for (int k = 0; k < 2; k++) {
        const float2* Gp = g_G + (size_t)(s0 + k) * (NKY * 128);
        for (int i = tid; i < NKY * 128; i += 320) {
            int ky = i >> 7, h = i & 127;
            Gs[k][h * NKY + ky] = Gp[i];    // coalesced read, conflict-free write
        }
    }
    __syncthreads();

    if (tid < 17 * NKY) {
        const int a = tid / NKY, ky = tid - a * NKY;
        float cw, sw;
        sincospif((float)a * (1.0f / 64.0f), &sw, &cw);   // e^{i 2pi a/128}

        float C1[2], C2[2], S1[2], S2[2];
        const float sgn = (a & 1) ? -1.f : 1.f;
        #pragma unroll
        for (int k = 0; k < 2; k++) {
            float2 g0  = Gs[k][0 * NKY + ky];
            float2 g64 = Gs[k][64 * NKY + ky];
            C1[k] = g0.x + sgn * g64.x;
            C2[k] = g0.y + sgn * g64.y;
            S1[k] = 0.f; S2[k] = 0.f;
        }

        float tc = cw, ts = sw;                 // (cos, sin)(a*h*t), h starts at 1
        #pragma unroll 3
        for (int h = 1; h < 64; h++) {
            #pragma unroll
            for (int k = 0; k < 2; k++) {
                float2 ga = Gs[k][h * NKY + ky];
                float2 gb = Gs[k][(128 - h) * NKY + ky];
                float pr = ga.x + gb.x, pi = ga.y + gb.y;
                float mr = ga.x - gb.x, mi = ga.y - gb.y;
                C1[k] = fmaf(tc, pr, C1[k]);
                C2[k] = fmaf(tc, pi, C2[k]);
                S1[k] = fmaf(ts, mr, S1[k]);
                S2[k] = fmaf(ts, mi, S2[k]);
            }
            float nc = fmaf(tc, cw, -ts * sw);
            ts = fmaf(tc, sw,  ts * cw);
            tc = nc;
        }

        const float inv = 1.0f / 16384.0f;
        #pragma unroll
        for (int k = 0; k < 2; k++) {
            const int s = s0 + k, b = s >> 7, c = s & 127;
            float2* Xfb = g_Xf + (size_t)c * (NMODE * 8) + b;
            Xfb[(a * NKY + ky) * 8] =
                make_float2((C1[k] + S2[k]) * inv, (C2[k] - S1[k]) * inv);
            if (a >= 1 && a <= 15)
                Xfb[((32 - a) * NKY + ky) * 8] =
                    make_float2((C1[k] - S2[k]) * inv, (C2[k] + S1[k]) * inv);
        }
    }
}

// ===========================================================================
// Kernel 2: spectral channel mix, skew-Hermitian weight built on the fly.
//   Y[b,c,m] = sum_ct [(re[c,ct,m]-re[ct,c,m]) + i(im[c,ct,m]+im[ct,c,m])] Xf[b,ct,m]
// grid (17 m-tiles x 16 c-tiles), block 256 = 32 m x 8 c. Thread = (c, m),
// 8 batch complex accumulators; Xf loads are 4x LDG.128 (batches contiguous).
// ===========================================================================
__global__ __launch_bounds__(256) void k_mix(const float* __restrict__ re,
                                             const float* __restrict__ im) {
    const int mi = threadIdx.x & 31;
    const int ci = threadIdx.x >> 5;
    const int m  = blockIdx.x * 32 + mi;
    const int c  = blockIdx.y * 8 + ci;

    float yr[8], yi[8];
    #pragma unroll
    for (int b = 0; b < 8; b++) { yr[b] = 0.f; yi[b] = 0.f; }

    const float* reA = re + (size_t)c * (128 * NMODE) + m;   // [c][ct][m]
    const float* reB = re + (size_t)c * NMODE + m;           // [ct][c][m]
    const float* imA = im + (size_t)c * (128 * NMODE) + m;
    const float* imB = im + (size_t)c * NMODE + m;
    const float4* xb = (const float4*)g_Xf + (size_t)m * 4;  // [ct][m][b0..7]

    #pragma unroll 2
    for (int ct = 0; ct < 128; ct++) {
        float wre = reA[ct * NMODE] - reB[ct * (128 * NMODE)];
        float wim = imA[ct * NMODE] + imB[ct * (128 * NMODE)];
        const float4* x4 = xb + (size_t)ct * (NMODE * 4);
        float4 x0 = x4[0], x1 = x4[1], x2 = x4[2], x3 = x4[3];
        yr[0]=fmaf(wre,x0.x,fmaf(-wim,x0.y,yr[0])); yi[0]=fmaf(wre,x0.y,fmaf(wim,x0.x,yi[0]));
        yr[1]=fmaf(wre,x0.z,fmaf(-wim,x0.w,yr[1])); yi[1]=fmaf(wre,x0.w,fmaf(wim,x0.z,yi[1]));
        yr[2]=fmaf(wre,x1.x,fmaf(-wim,x1.y,yr[2])); yi[2]=fmaf(wre,x1.y,fmaf(wim,x1.x,yi[2]));
        yr[3]=fmaf(wre,x1.z,fmaf(-wim,x1.w,yr[3])); yi[3]=fmaf(wre,x1.w,fmaf(wim,x1.z,yi[3]));
        yr[4]=fmaf(wre,x2.x,fmaf(-wim,x2.y,yr[4])); yi[4]=fmaf(wre,x2.y,fmaf(wim,x2.x,yi[4]));
        yr[5]=fmaf(wre,x2.z,fmaf(-wim,x2.w,yr[5])); yi[5]=fmaf(wre,x2.w,fmaf(wim,x2.z,yi[5]));
        yr[6]=fmaf(wre,x3.x,fmaf(-wim,x3.y,yr[6])); yi[6]=fmaf(wre,x3.y,fmaf(wim,x3.x,yi[6]));
        yr[7]=fmaf(wre,x3.z,fmaf(-wim,x3.w,yr[7])); yi[7]=fmaf(wre,x3.w,fmaf(wim,x3.z,yi[7]));
    }
    #pragma unroll
    for (int b = 0; b < 8; b++)
        g_Y[(size_t)(b * 128 + c) * NMODE + m] = make_float2(yr[b], yi[b]);
}

// ===========================================================================
// Kernel 3a: kx -> h synthesis (folded), rotation-generated trig, 4 h/thread.
//   P[a]=Y[+a]+Y[-a], M[a]=Y[+a]-Y[-a]
//   Z[h]=(C1-S2, C2+S1), Z[128-h]=(C1+S2, C2-S1)
// Thread t<272: ky=t%17, hb=t/17 in 0..15, h = hb+{0,16,32,48} (shared Pa/Ma
// loads, 4 independent rotation chains). Threads 272..288: h=64 (sin=0).
// ===========================================================================
__global__ __launch_bounds__(320) void k_inv1() {
    __shared__ float2 Pa[NKY * NKY];     // [a][ky]
    __shared__ float2 Ma[NKY * NKY];

    const int tid = threadIdx.x;
    const float2* Yp = g_Y + (size_t)blockIdx.x * NMODE;

    if (tid < 17 * NKY) {
        int a = tid / NKY, ky = tid - a * NKY;
        float2 yp = Yp[a * NKY + ky];
        float2 P, M;
        if (a == 0)       { P = yp; M = make_float2(0.f, 0.f); }
        else if (a == 16) { P = yp; M = yp; }
        else {
            float2 yn = Yp[(32 - a) * NKY + ky];
            P = make_float2(yp.x + yn.x, yp.y + yn.y);
            M = make_float2(yp.x - yn.x, yp.y - yn.y);
        }
        Pa[tid] = P;
        Ma[tid] = M;
    }
    __syncthreads();

    float2* Zp = g_Z + (size_t)blockIdx.x * (128 * NKY);

    if (tid < 272) {
        const int ky = tid % NKY;
        const int hb = tid / NKY;           // 0..15
        float cw[4], sw[4], tc[4], ts[4];
        float C1[4], C2[4], S1[4], S2[4];
        #pragma unroll
        for (int j = 0; j < 4; j++) {
            int h = hb + 16 * j;
            sincospif((float)h * (1.0f / 64.0f), &sw[j], &cw[j]);  // e^{i 2pi h/128}
            tc[j] = 1.f; ts[j] = 0.f;
            C1[j] = 0.f; C2[j] = 0.f; S1[j] = 0.f; S2[j] = 0.f;
        }
        #pragma unroll
        for (int a = 0; a < NKY; a++) {
            float2 P = Pa[a * NKY + ky];
            float2 M = Ma[a * NKY + ky];
            #pragma unroll
            for (int j = 0; j < 4; j++) {
                C1[j] = fmaf(tc[j], P.x, C1[j]);
                C2[j] = fmaf(tc[j], P.y, C2[j]);
                S1[j] = fmaf(ts[j], M.x, S1[j]);
                S2[j] = fmaf(ts[j], M.y, S2[j]);
                float nc = fmaf(tc[j], cw[j], -ts[j] * sw[j]);
                ts[j] = fmaf(tc[j], sw[j],  ts[j] * cw[j]);
                tc[j] = nc;
            }
        }
        #pragma unroll
        for (int j = 0; j < 4; j++) {
            int h = hb + 16 * j;
            Zp[h * NKY + ky] = make_float2(C1[j] - S2[j], C2[j] + S1[j]);
            if (h >= 1)
                Zp[(128 - h) * NKY + ky] = make_float2(C1[j] + S2[j], C2[j] - S1[j]);
        }
    } else if (tid < 289) {
        // h = 64: cos(pi a) = (-1)^a, sin = 0
        const int ky = tid - 272;
        float C1 = 0.f, C2 = 0.f;
        #pragma unroll
        for (int a = 0; a < NKY; a++) {
            float2 P = Pa[a * NKY + ky];
            float sg = (a & 1) ? -1.f : 1.f;
            C1 = fmaf(sg, P.x, C1);
            C2 = fmaf(sg, P.y, C2);
        }
        Zp[64 * NKY + ky] = make_float2(C1, C2);
    }
}

// ===========================================================================
// Kernel 3b: ky -> w synthesis (c2r), emit w and 128-w; then w=64 column.
//   out[h][w] = C - S, out[h][128-w] = C + S
//   C = sum a_ky Zre cos(t ky w), S = sum a_ky Zim sin(t ky w), a_0=1 else 2.
// ===========================================================================
__global__ __launch_bounds__(256) void k_inv2(float* __restrict__ out) {
    __shared__ float2 tb[128];
    __shared__ float2 Zs[128][18];      // pad 18 -> 16B-aligned float4 rows

    const int tid = threadIdx.x;
    if (tid < 128) {
        float s, c;
        sincospif((float)tid * (2.0f / 128.0f), &s, &c);
        tb[tid] = make_float2(c, s);
    }
    const float2* Zp = g_Z + (size_t)blockIdx.x * (128 * NKY);
    for (int i = tid; i < 128 * NKY; i += 256) {
        int h = i / NKY, ky = i - h * NKY;
        Zs[h][ky] = Zp[i];
    }
    __syncthreads();

    float* op = out + (size_t)blockIdx.x * 16384;

    const int w  = tid & 63;
    const int h0 = (tid >> 6) * 32;
    float ck[NKY], sk[NKY];
    #pragma unroll
    for (int ky = 0; ky < NKY; ky++) {
        float2 t = tb[(ky * w) & 127];
        float a = ky ? 2.0f : 1.0f;
        ck[ky] = a * t.x;
        sk[ky] = a * t.y;
    }
    for (int h = h0; h < h0 + 32; h++) {
        const float4* zp = (const float4*)(&Zs[h][0]);
        float C = 0.f, S = 0.f;
        #pragma unroll
        for (int j = 0; j < 8; j++) {
            float4 q = zp[j];
            C = fmaf(ck[2 * j],     q.x, C);
            S = fmaf(sk[2 * j],     q.y, S);
            C = fmaf(ck[2 * j + 1], q.z, C);
            S = fmaf(sk[2 * j + 1], q.w, S);
        }
        float2 z16 = Zs[h][16];
        C = fmaf(ck[16], z16.x, C);
        S = fmaf(sk[16], z16.y, S);
        op[h * 128 + w] = C - S;
        if (w) op[h * 128 + 128 - w] = C + S;
    }

    // w = 64 column: cos(pi ky) = (-1)^ky, sin = 0
    if (tid < 128) {
        int h = tid;
        float E = 0.f;
        #pragma unroll
        for (int ky = 0; ky < NKY; ky++) {
            float a = ky ? 2.0f : 1.0f;
            float c = (ky & 1) ? -a : a;
            E = fmaf(c, Zs[h][ky].x, E);
        }
        op[h * 128 + 64] = E;
    }
}

extern "C" void kernel_launch(void* const* d_in, const int* in_sizes, int n_in,
                              void* d_out, int out_size) {
    const float* X  = (const float*)d_in[0];
    const float* re = (const float*)d_in[1];
    const float* im = (const float*)d_in[2];
    float* out = (float*)d_out;

    k_fwd1<<<NSLICE, 256>>>(X);
    k_fwd2<<<NSLICE / 2, 320>>>();
    k_mix<<<dim3(17, 16), 256>>>(re, im);
    k_inv1<<<NSLICE, 320>>>();
    k_inv2<<<NSLICE, 256>>>(out);
}